// round 1
// baseline (speedup 1.0000x reference)
#include <cuda_runtime.h>
#include <cuda_bf16.h>

#define N_NODES 100000
#define F_IN    500
#define H_DIM   64
#define C_DIM   10
#define N_EDGES 1600000

// ---------------- scratch (device globals; no allocation) ----------------
__device__ __align__(16) float g_deg[N_NODES];
__device__ __align__(16) float g_dis[N_NODES];
__device__ __align__(256) float g_h1[N_NODES * H_DIM];     // x @ W1
__device__ __align__(256) float g_agg1[N_NODES * H_DIM];   // scatter accum layer 1, then relu'd h
__device__ __align__(256) float g_h2[N_NODES * C_DIM];     // h_relu @ W2
__device__ __align__(256) float g_agg2[N_NODES * 12];      // padded stride-12 so d*12*4B is 16B-aligned

// ---------------- vector RED helpers ----------------
__device__ __forceinline__ void red_add_v4(float* addr, float a, float b, float c, float d) {
    asm volatile("red.global.add.v4.f32 [%0], {%1, %2, %3, %4};"
                 :: "l"(addr), "f"(a), "f"(b), "f"(c), "f"(d) : "memory");
}
__device__ __forceinline__ void red_add_v2(float* addr, float a, float b) {
    asm volatile("red.global.add.v2.f32 [%0], {%1, %2};"
                 :: "l"(addr), "f"(a), "f"(b) : "memory");
}

// ---------------- init: zero accumulators, deg = 1 (self loop) ----------------
__global__ void init_kernel() {
    int i = blockIdx.x * blockDim.x + threadIdx.x;
    if (i < N_NODES * H_DIM) g_agg1[i] = 0.f;
    if (i < N_NODES * 12)    g_agg2[i] = 0.f;
    if (i < N_NODES)         g_deg[i]  = 1.0f;
}

// ---------------- degree over dst ----------------
__global__ void degree_kernel(const int* __restrict__ dst) {
    int e = blockIdx.x * blockDim.x + threadIdx.x;
    if (e < N_EDGES) atomicAdd(&g_deg[dst[e]], 1.0f);
}

__global__ void rsqrt_kernel() {
    int i = blockIdx.x * blockDim.x + threadIdx.x;
    if (i < N_NODES) g_dis[i] = rsqrtf(g_deg[i]);
}

// ---------------- GEMM1: h1[N,64] = x[N,500] @ W1[500,64] ----------------
// BM=64, BN=64, BK=16, 16x16 threads, 4x4 per thread.
#define BM 64
#define BN 64
#define BK 16
__global__ __launch_bounds__(256) void gemm1_kernel(const float* __restrict__ X,
                                                    const float* __restrict__ W) {
    __shared__ float As[BM][BK + 1];
    __shared__ float Bs[BK][BN];
    const int block_row = blockIdx.x * BM;
    const int tx = threadIdx.x & 15;
    const int ty = threadIdx.x >> 4;

    float acc[4][4];
#pragma unroll
    for (int i = 0; i < 4; i++)
#pragma unroll
        for (int j = 0; j < 4; j++) acc[i][j] = 0.f;

    for (int k0 = 0; k0 < F_IN; k0 += BK) {
#pragma unroll
        for (int i = 0; i < 4; i++) {
            int idx = threadIdx.x + i * 256;      // 0..1023
            int r = idx >> 4, c = idx & 15;
            int gr = block_row + r, gc = k0 + c;
            As[r][c] = (gr < N_NODES && gc < F_IN) ? X[(size_t)gr * F_IN + gc] : 0.f;
        }
#pragma unroll
        for (int i = 0; i < 4; i++) {
            int idx = threadIdx.x + i * 256;
            int r = idx >> 6, c = idx & 63;
            int gk = k0 + r;
            Bs[r][c] = (gk < F_IN) ? W[gk * H_DIM + c] : 0.f;
        }
        __syncthreads();
#pragma unroll
        for (int k = 0; k < BK; k++) {
            float a0 = As[ty * 4 + 0][k];
            float a1 = As[ty * 4 + 1][k];
            float a2 = As[ty * 4 + 2][k];
            float a3 = As[ty * 4 + 3][k];
            float4 b = *(const float4*)&Bs[k][tx * 4];
            acc[0][0] += a0 * b.x; acc[0][1] += a0 * b.y; acc[0][2] += a0 * b.z; acc[0][3] += a0 * b.w;
            acc[1][0] += a1 * b.x; acc[1][1] += a1 * b.y; acc[1][2] += a1 * b.z; acc[1][3] += a1 * b.w;
            acc[2][0] += a2 * b.x; acc[2][1] += a2 * b.y; acc[2][2] += a2 * b.z; acc[2][3] += a2 * b.w;
            acc[3][0] += a3 * b.x; acc[3][1] += a3 * b.y; acc[3][2] += a3 * b.z; acc[3][3] += a3 * b.w;
        }
        __syncthreads();
    }
#pragma unroll
    for (int i = 0; i < 4; i++) {
        int gr = block_row + ty * 4 + i;
        if (gr < N_NODES) {
            float4 v = make_float4(acc[i][0], acc[i][1], acc[i][2], acc[i][3]);
            *(float4*)&g_h1[(size_t)gr * H_DIM + tx * 4] = v;
        }
    }
}

// ---------------- edge aggregation layer 1: 16 threads/edge, 4 feats each ----------------
__global__ void agg1_kernel(const int* __restrict__ src, const int* __restrict__ dst) {
    long long gid = (long long)blockIdx.x * blockDim.x + threadIdx.x;
    if (gid >= (long long)N_EDGES * 16) return;
    int e = (int)(gid >> 4);
    int c = ((int)gid & 15) << 2;
    int s = __ldg(&src[e]);
    int d = __ldg(&dst[e]);
    float norm = g_dis[s] * g_dis[d];
    float4 v = *(const float4*)(g_h1 + ((size_t)s << 6) + c);
    red_add_v4(g_agg1 + ((size_t)d << 6) + c,
               v.x * norm, v.y * norm, v.z * norm, v.w * norm);
}

// ---------------- self-loop + bias + ReLU (in-place on g_agg1) ----------------
__global__ void post1_kernel(const float* __restrict__ b1) {
    int idx = blockIdx.x * blockDim.x + threadIdx.x;
    if (idx >= N_NODES * H_DIM) return;
    int i = idx >> 6;
    int f = idx & 63;
    float dd = g_dis[i];
    float v = g_agg1[idx] + g_h1[idx] * dd * dd + __ldg(&b1[f]);
    g_agg1[idx] = fmaxf(v, 0.f);
}

// ---------------- GEMM2: h2[N,10] = h_relu[N,64] @ W2[64,10] ----------------
__global__ __launch_bounds__(256) void gemm2_kernel(const float* __restrict__ W2) {
    __shared__ float Ws[H_DIM * C_DIM];
    for (int i = threadIdx.x; i < H_DIM * C_DIM; i += blockDim.x) Ws[i] = W2[i];
    __syncthreads();
    int row = blockIdx.x * blockDim.x + threadIdx.x;
    if (row >= N_NODES) return;
    float acc[C_DIM];
#pragma unroll
    for (int j = 0; j < C_DIM; j++) acc[j] = 0.f;
    const float4* rp = (const float4*)(g_agg1 + (size_t)row * H_DIM);
#pragma unroll
    for (int k4 = 0; k4 < H_DIM / 4; k4++) {
        float4 v = rp[k4];
        int k = k4 * 4;
#pragma unroll
        for (int j = 0; j < C_DIM; j++) {
            acc[j] += v.x * Ws[(k + 0) * C_DIM + j]
                    + v.y * Ws[(k + 1) * C_DIM + j]
                    + v.z * Ws[(k + 2) * C_DIM + j]
                    + v.w * Ws[(k + 3) * C_DIM + j];
        }
    }
#pragma unroll
    for (int j = 0; j < C_DIM; j++) g_h2[(size_t)row * C_DIM + j] = acc[j];
}

// ---------------- edge aggregation layer 2: 1 thread/edge, 10 feats, padded stride 12 ----------------
__global__ void agg2_kernel(const int* __restrict__ src, const int* __restrict__ dst) {
    int e = blockIdx.x * blockDim.x + threadIdx.x;
    if (e >= N_EDGES) return;
    int s = __ldg(&src[e]);
    int d = __ldg(&dst[e]);
    float norm = g_dis[s] * g_dis[d];
    const float2* hp = (const float2*)(g_h2 + (size_t)s * C_DIM);  // 8B-aligned: 40*s
    float2 p0 = hp[0], p1 = hp[1], p2 = hp[2], p3 = hp[3], p4 = hp[4];
    float* base = g_agg2 + (size_t)d * 12;                         // 48*d bytes: 16B-aligned
    red_add_v4(base,     p0.x * norm, p0.y * norm, p1.x * norm, p1.y * norm);
    red_add_v4(base + 4, p2.x * norm, p2.y * norm, p3.x * norm, p3.y * norm);
    red_add_v2(base + 8, p4.x * norm, p4.y * norm);
}

// ---------------- final: out = agg2 + self-loop + bias ----------------
__global__ void final_kernel(const float* __restrict__ b2, float* __restrict__ out) {
    int idx = blockIdx.x * blockDim.x + threadIdx.x;
    if (idx >= N_NODES * C_DIM) return;
    int i = idx / C_DIM;
    int j = idx - i * C_DIM;
    float dd = g_dis[i];
    out[idx] = g_agg2[(size_t)i * 12 + j] + g_h2[idx] * dd * dd + __ldg(&b2[j]);
}

// ---------------- launch ----------------
extern "C" void kernel_launch(void* const* d_in, const int* in_sizes, int n_in,
                              void* d_out, int out_size) {
    const float* x  = (const float*)d_in[0];
    const int*   ei = (const int*)d_in[1];
    const float* W1 = (const float*)d_in[2];
    const float* b1 = (const float*)d_in[3];
    const float* W2 = (const float*)d_in[4];
    const float* b2 = (const float*)d_in[5];
    float* out = (float*)d_out;

    const int E = in_sizes[1] / 2;         // 1600000
    const int* src = ei;
    const int* dst = ei + E;

    const int T = 256;

    // init scratch
    init_kernel<<<(N_NODES * H_DIM + T - 1) / T, T>>>();

    // degree + normalization
    degree_kernel<<<(E + T - 1) / T, T>>>(dst);
    rsqrt_kernel<<<(N_NODES + T - 1) / T, T>>>();

    // layer 1
    gemm1_kernel<<<(N_NODES + BM - 1) / BM, 256>>>(x, W1);
    {
        long long total = (long long)E * 16;
        int blocks = (int)((total + T - 1) / T);
        agg1_kernel<<<blocks, T>>>(src, dst);
    }
    post1_kernel<<<(N_NODES * H_DIM + T - 1) / T, T>>>(b1);

    // layer 2
    gemm2_kernel<<<(N_NODES + T - 1) / T, T>>>(W2);
    agg2_kernel<<<(E + T - 1) / T, T>>>(src, dst);
    final_kernel<<<(N_NODES * C_DIM + T - 1) / T, T>>>(b2, out);
}

// round 3
// speedup vs baseline: 1.4139x; 1.4139x over previous
#include <cuda_runtime.h>
#include <cuda_bf16.h>
#include <cstdint>

#define N_NODES 100000
#define F_IN    500
#define H_DIM   64
#define C_DIM   10
#define N_EDGES 1600000

// ---------------- scratch (device globals; no allocation) ----------------
__device__ __align__(16) float g_deg[N_NODES];
__device__ __align__(16) float g_dis[N_NODES];
__device__ __align__(256) float g_h1[N_NODES * H_DIM];     // x @ W1
__device__ __align__(256) float g_agg1[N_NODES * H_DIM];   // scatter accum layer 1, then relu'd h
__device__ __align__(256) float g_h2[N_NODES * C_DIM];     // h_relu @ W2
__device__ __align__(256) float g_agg2[N_NODES * 12];      // padded stride-12 (16B-aligned rows)

// pre-split W1^T: [64 n][512 k] row-major bf16 hi/lo (k >= 500 zero-padded)
__device__ __align__(16) __nv_bfloat16 g_wt_hi[64 * 512];
__device__ __align__(16) __nv_bfloat16 g_wt_lo[64 * 512];

// ---------------- helpers ----------------
__device__ __forceinline__ void red_add_v4(float* addr, float a, float b, float c, float d) {
    asm volatile("red.global.add.v4.f32 [%0], {%1, %2, %3, %4};"
                 :: "l"(addr), "f"(a), "f"(b), "f"(c), "f"(d) : "memory");
}
__device__ __forceinline__ void red_add_v2(float* addr, float a, float b) {
    asm volatile("red.global.add.v2.f32 [%0], {%1, %2};"
                 :: "l"(addr), "f"(a), "f"(b) : "memory");
}
__device__ __forceinline__ void mma16816(float* c, const uint32_t* a, const uint32_t* b) {
    asm volatile("mma.sync.aligned.m16n8k16.row.col.f32.bf16.bf16.f32 "
                 "{%0,%1,%2,%3}, {%4,%5,%6,%7}, {%8,%9}, {%0,%1,%2,%3};"
                 : "+f"(c[0]), "+f"(c[1]), "+f"(c[2]), "+f"(c[3])
                 : "r"(a[0]), "r"(a[1]), "r"(a[2]), "r"(a[3]), "r"(b[0]), "r"(b[1]));
}
__device__ __forceinline__ uint32_t pack_bf16x2(float x, float y) {
    __nv_bfloat16 bx = __float2bfloat16(x);
    __nv_bfloat16 by = __float2bfloat16(y);
    return (uint32_t)__bfloat16_as_ushort(bx) | ((uint32_t)__bfloat16_as_ushort(by) << 16);
}

// ---------------- init: zero accumulators, deg = 1 (self loop) ----------------
__global__ void init_kernel() {
    int i = blockIdx.x * blockDim.x + threadIdx.x;
    if (i < N_NODES * H_DIM) g_agg1[i] = 0.f;
    if (i < N_NODES * 12)    g_agg2[i] = 0.f;
    if (i < N_NODES)         g_deg[i]  = 1.0f;
}

// ---------------- degree over dst ----------------
__global__ void degree_kernel(const int* __restrict__ dst) {
    int e = blockIdx.x * blockDim.x + threadIdx.x;
    if (e < N_EDGES) atomicAdd(&g_deg[dst[e]], 1.0f);
}

__global__ void rsqrt_kernel() {
    int i = blockIdx.x * blockDim.x + threadIdx.x;
    if (i < N_NODES) g_dis[i] = rsqrtf(g_deg[i]);
}

// ---------------- prep: split + transpose W1 -> bf16 hi/lo [64][512] ----------------
__global__ void prep_w_kernel(const float* __restrict__ W1) {
    int idx = blockIdx.x * blockDim.x + threadIdx.x;   // 0 .. 32767
    int n = idx >> 9;          // 0..63
    int k = idx & 511;         // 0..511
    float w = (k < F_IN) ? W1[k * H_DIM + n] : 0.f;
    __nv_bfloat16 hi = __float2bfloat16(w);
    __nv_bfloat16 lo = __float2bfloat16(w - __bfloat162float(hi));
    g_wt_hi[n * 512 + k] = hi;
    g_wt_lo[n * 512 + k] = lo;
}

// ---------------- GEMM1 via mma.sync bf16 3-term split ----------------
// h1[N,64] = X[N,500] @ W1[500,64];  M-tile 128, K chunks of 32.
// SMEM row stride 80B -> fragment LDS pattern is conflict-free (20r+c covers all banks).
#define MT      128
#define KCH     32
#define NCHUNK  16
#define A_STRIDE 80
#define B_STRIDE 80

__global__ __launch_bounds__(256) void gemm1_mma_kernel(const float* __restrict__ X) {
    __shared__ __align__(16) char smA_hi[MT * A_STRIDE];
    __shared__ __align__(16) char smA_lo[MT * A_STRIDE];
    __shared__ __align__(16) char smB_hi[64 * B_STRIDE];
    __shared__ __align__(16) char smB_lo[64 * B_STRIDE];

    const int tid  = threadIdx.x;
    const int wid  = tid >> 5;
    const int lane = tid & 31;
    const int row0 = blockIdx.x * MT;

    float acc[8][4];
#pragma unroll
    for (int g = 0; g < 8; g++)
#pragma unroll
        for (int j = 0; j < 4; j++) acc[g][j] = 0.f;

    const int a_c4 = tid & 7;       // float4 column (cols a_c4*4 .. +3 within chunk)
    const int a_r  = tid >> 3;      // row 0..31 per pass
    const int b_n  = tid >> 2;      // 0..63
    const int b_kg = tid & 3;       // 8-elem k group

    const int frag_m  = (lane >> 2);        // 0..7
    const int frag_kb = (lane & 3) * 4;     // byte offset of k pair

    for (int ch = 0; ch < NCHUNK; ch++) {
        const int k0 = ch * KCH;

        // --- A: fp32 global -> split bf16 hi/lo in SMEM ---
#pragma unroll
        for (int p = 0; p < 4; p++) {
            int r  = p * 32 + a_r;
            int gr = row0 + r;
            int gc = k0 + a_c4 * 4;
            float4 v = make_float4(0.f, 0.f, 0.f, 0.f);
            if (gr < N_NODES && gc < F_IN)
                v = *(const float4*)(X + (size_t)gr * F_IN + gc);
            __nv_bfloat16 h0 = __float2bfloat16(v.x), h1 = __float2bfloat16(v.y);
            __nv_bfloat16 h2 = __float2bfloat16(v.z), h3 = __float2bfloat16(v.w);
            uint32_t hiA = (uint32_t)__bfloat16_as_ushort(h0) | ((uint32_t)__bfloat16_as_ushort(h1) << 16);
            uint32_t hiB = (uint32_t)__bfloat16_as_ushort(h2) | ((uint32_t)__bfloat16_as_ushort(h3) << 16);
            uint32_t loA = pack_bf16x2(v.x - __bfloat162float(h0), v.y - __bfloat162float(h1));
            uint32_t loB = pack_bf16x2(v.z - __bfloat162float(h2), v.w - __bfloat162float(h3));
            *(uint2*)(smA_hi + r * A_STRIDE + a_c4 * 8) = make_uint2(hiA, hiB);
            *(uint2*)(smA_lo + r * A_STRIDE + a_c4 * 8) = make_uint2(loA, loB);
        }
        // --- B: copy pre-split chunk (64 x 32 bf16) ---
        {
            const char* srch = (const char*)g_wt_hi + (size_t)b_n * 1024 + (k0 + b_kg * 8) * 2;
            const char* srcl = (const char*)g_wt_lo + (size_t)b_n * 1024 + (k0 + b_kg * 8) * 2;
            *(uint4*)(smB_hi + b_n * B_STRIDE + b_kg * 16) = *(const uint4*)srch;
            *(uint4*)(smB_lo + b_n * B_STRIDE + b_kg * 16) = *(const uint4*)srcl;
        }
        __syncthreads();

        // --- compute: 2 k16-steps x 8 n-groups x 3 split terms ---
#pragma unroll
        for (int ks = 0; ks < 2; ks++) {
            const int m0   = wid * 16 + frag_m;
            const int koff = ks * 32 + frag_kb;
            uint32_t ahi[4], alo[4];
            ahi[0] = *(const uint32_t*)(smA_hi + m0 * A_STRIDE + koff);
            ahi[1] = *(const uint32_t*)(smA_hi + (m0 + 8) * A_STRIDE + koff);
            ahi[2] = *(const uint32_t*)(smA_hi + m0 * A_STRIDE + koff + 16);
            ahi[3] = *(const uint32_t*)(smA_hi + (m0 + 8) * A_STRIDE + koff + 16);
            alo[0] = *(const uint32_t*)(smA_lo + m0 * A_STRIDE + koff);
            alo[1] = *(const uint32_t*)(smA_lo + (m0 + 8) * A_STRIDE + koff);
            alo[2] = *(const uint32_t*)(smA_lo + m0 * A_STRIDE + koff + 16);
            alo[3] = *(const uint32_t*)(smA_lo + (m0 + 8) * A_STRIDE + koff + 16);
#pragma unroll
            for (int g = 0; g < 8; g++) {
                const int n = g * 8 + frag_m;
                uint32_t bhi[2], blo[2];
                bhi[0] = *(const uint32_t*)(smB_hi + n * B_STRIDE + koff);
                bhi[1] = *(const uint32_t*)(smB_hi + n * B_STRIDE + koff + 16);
                blo[0] = *(const uint32_t*)(smB_lo + n * B_STRIDE + koff);
                blo[1] = *(const uint32_t*)(smB_lo + n * B_STRIDE + koff + 16);
                mma16816(acc[g], ahi, bhi);
                mma16816(acc[g], alo, bhi);
                mma16816(acc[g], ahi, blo);
            }
        }
        __syncthreads();
    }

    // --- epilogue: fragments -> g_h1 ---
    {
        const int m0 = row0 + wid * 16 + frag_m;
        const int nc = (lane & 3) * 2;
#pragma unroll
        for (int g = 0; g < 8; g++) {
            if (m0 < N_NODES)
                *(float2*)(g_h1 + (size_t)m0 * H_DIM + g * 8 + nc) = make_float2(acc[g][0], acc[g][1]);
            if (m0 + 8 < N_NODES)
                *(float2*)(g_h1 + (size_t)(m0 + 8) * H_DIM + g * 8 + nc) = make_float2(acc[g][2], acc[g][3]);
        }
    }
}

// ---------------- edge aggregation layer 1: 16 threads/edge, 4 feats each ----------------
__global__ void agg1_kernel(const int* __restrict__ src, const int* __restrict__ dst) {
    long long gid = (long long)blockIdx.x * blockDim.x + threadIdx.x;
    if (gid >= (long long)N_EDGES * 16) return;
    int e = (int)(gid >> 4);
    int c = ((int)gid & 15) << 2;
    int s = __ldg(&src[e]);
    int d = __ldg(&dst[e]);
    float norm = g_dis[s] * g_dis[d];
    float4 v = *(const float4*)(g_h1 + ((size_t)s << 6) + c);
    red_add_v4(g_agg1 + ((size_t)d << 6) + c,
               v.x * norm, v.y * norm, v.z * norm, v.w * norm);
}

// ---------------- self-loop + bias + ReLU (in-place on g_agg1) ----------------
__global__ void post1_kernel(const float* __restrict__ b1) {
    int idx = blockIdx.x * blockDim.x + threadIdx.x;
    if (idx >= N_NODES * H_DIM) return;
    int i = idx >> 6;
    int f = idx & 63;
    float dd = g_dis[i];
    float v = g_agg1[idx] + g_h1[idx] * dd * dd + __ldg(&b1[f]);
    g_agg1[idx] = fmaxf(v, 0.f);
}

// ---------------- GEMM2: h2[N,10] = h_relu[N,64] @ W2[64,10] ----------------
__global__ __launch_bounds__(256) void gemm2_kernel(const float* __restrict__ W2) {
    __shared__ float Ws[H_DIM * C_DIM];
    for (int i = threadIdx.x; i < H_DIM * C_DIM; i += blockDim.x) Ws[i] = W2[i];
    __syncthreads();
    int row = blockIdx.x * blockDim.x + threadIdx.x;
    if (row >= N_NODES) return;
    float acc[C_DIM];
#pragma unroll
    for (int j = 0; j < C_DIM; j++) acc[j] = 0.f;
    const float4* rp = (const float4*)(g_agg1 + (size_t)row * H_DIM);
#pragma unroll
    for (int k4 = 0; k4 < H_DIM / 4; k4++) {
        float4 v = rp[k4];
        int k = k4 * 4;
#pragma unroll
        for (int j = 0; j < C_DIM; j++) {
            acc[j] += v.x * Ws[(k + 0) * C_DIM + j]
                    + v.y * Ws[(k + 1) * C_DIM + j]
                    + v.z * Ws[(k + 2) * C_DIM + j]
                    + v.w * Ws[(k + 3) * C_DIM + j];
        }
    }
#pragma unroll
    for (int j = 0; j < C_DIM; j++) g_h2[(size_t)row * C_DIM + j] = acc[j];
}

// ---------------- edge aggregation layer 2 ----------------
__global__ void agg2_kernel(const int* __restrict__ src, const int* __restrict__ dst) {
    int e = blockIdx.x * blockDim.x + threadIdx.x;
    if (e >= N_EDGES) return;
    int s = __ldg(&src[e]);
    int d = __ldg(&dst[e]);
    float norm = g_dis[s] * g_dis[d];
    const float2* hp = (const float2*)(g_h2 + (size_t)s * C_DIM);
    float2 p0 = hp[0], p1 = hp[1], p2 = hp[2], p3 = hp[3], p4 = hp[4];
    float* base = g_agg2 + (size_t)d * 12;
    red_add_v4(base,     p0.x * norm, p0.y * norm, p1.x * norm, p1.y * norm);
    red_add_v4(base + 4, p2.x * norm, p2.y * norm, p3.x * norm, p3.y * norm);
    red_add_v2(base + 8, p4.x * norm, p4.y * norm);
}

// ---------------- final: out = agg2 + self-loop + bias ----------------
__global__ void final_kernel(const float* __restrict__ b2, float* __restrict__ out) {
    int idx = blockIdx.x * blockDim.x + threadIdx.x;
    if (idx >= N_NODES * C_DIM) return;
    int i = idx / C_DIM;
    int j = idx - i * C_DIM;
    float dd = g_dis[i];
    out[idx] = g_agg2[(size_t)i * 12 + j] + g_h2[idx] * dd * dd + __ldg(&b2[j]);
}

// ---------------- launch ----------------
extern "C" void kernel_launch(void* const* d_in, const int* in_sizes, int n_in,
                              void* d_out, int out_size) {
    const float* x  = (const float*)d_in[0];
    const int*   ei = (const int*)d_in[1];
    const float* W1 = (const float*)d_in[2];
    const float* b1 = (const float*)d_in[3];
    const float* W2 = (const float*)d_in[4];
    const float* b2 = (const float*)d_in[5];
    float* out = (float*)d_out;

    const int E = in_sizes[1] / 2;         // 1600000
    const int* src = ei;
    const int* dst = ei + E;

    const int T = 256;

    // init scratch
    init_kernel<<<(N_NODES * H_DIM + T - 1) / T, T>>>();

    // degree + normalization
    degree_kernel<<<(E + T - 1) / T, T>>>(dst);
    rsqrt_kernel<<<(N_NODES + T - 1) / T, T>>>();

    // layer 1
    prep_w_kernel<<<128, 256>>>(W1);
    gemm1_mma_kernel<<<(N_NODES + MT - 1) / MT, 256>>>(x);
    {
        long long total = (long long)E * 16;
        int blocks = (int)((total + T - 1) / T);
        agg1_kernel<<<blocks, T>>>(src, dst);
    }
    post1_kernel<<<(N_NODES * H_DIM + T - 1) / T, T>>>(b1);

    // layer 2
    gemm2_kernel<<<(N_NODES + T - 1) / T, T>>>(W2);
    agg2_kernel<<<(E + T - 1) / T, T>>>(src, dst);
    final_kernel<<<(N_NODES * C_DIM + T - 1) / T, T>>>(b2, out);
}

// round 4
// speedup vs baseline: 1.8823x; 1.3313x over previous
#include <cuda_runtime.h>
#include <cuda_bf16.h>
#include <cstdint>

#define N_NODES 100000
#define F_IN    500
#define H_DIM   64
#define C_DIM   10
#define N_EDGES 1600000
#define NB_SCAN 391            // ceil(100000/256)

// ---------------- scratch (device globals; no allocation) ----------------
__device__ int   g_count[N_NODES];          // in-degree (excl self loop)
__device__ int   g_rowstart[N_NODES + 1];
__device__ int   g_cursor[N_NODES];
__device__ int   g_blocksum[512];
__device__ int   g_csr_src[N_EDGES];
__device__ __align__(16) float g_dis[N_NODES];
__device__ __align__(256) float g_h1[N_NODES * H_DIM];   // x @ W1
__device__ __align__(256) float g_hr[N_NODES * H_DIM];   // relu(gcn1)
__device__ __align__(256) float g_h2[N_NODES * C_DIM];   // h_relu @ W2

// pre-split W1^T: [64 n][512 k] row-major bf16 hi/lo (k >= 500 zero-padded)
__device__ __align__(16) __nv_bfloat16 g_wt_hi[64 * 512];
__device__ __align__(16) __nv_bfloat16 g_wt_lo[64 * 512];

// ---------------- helpers ----------------
__device__ __forceinline__ void mma16816(float* c, const uint32_t* a, const uint32_t* b) {
    asm volatile("mma.sync.aligned.m16n8k16.row.col.f32.bf16.bf16.f32 "
                 "{%0,%1,%2,%3}, {%4,%5,%6,%7}, {%8,%9}, {%0,%1,%2,%3};"
                 : "+f"(c[0]), "+f"(c[1]), "+f"(c[2]), "+f"(c[3])
                 : "r"(a[0]), "r"(a[1]), "r"(a[2]), "r"(a[3]), "r"(b[0]), "r"(b[1]));
}
__device__ __forceinline__ uint32_t pack_bf16x2(float x, float y) {
    __nv_bfloat16 bx = __float2bfloat16(x);
    __nv_bfloat16 by = __float2bfloat16(y);
    return (uint32_t)__bfloat16_as_ushort(bx) | ((uint32_t)__bfloat16_as_ushort(by) << 16);
}

// ---------------- graph preprocessing ----------------
__global__ void init_kernel() {
    int i = blockIdx.x * blockDim.x + threadIdx.x;
    if (i < N_NODES) g_count[i] = 0;
}

__global__ void degree_kernel(const int* __restrict__ dst) {
    int e = blockIdx.x * blockDim.x + threadIdx.x;
    if (e < N_EDGES) atomicAdd(&g_count[dst[e]], 1);
}

__global__ void dis_kernel() {
    int i = blockIdx.x * blockDim.x + threadIdx.x;
    if (i < N_NODES) g_dis[i] = rsqrtf((float)g_count[i] + 1.0f);
}

// exclusive scan of g_count -> g_rowstart (3-phase)
__global__ void scan1_kernel() {
    __shared__ int s[256];
    int i = blockIdx.x * 256 + threadIdx.x;
    int c = (i < N_NODES) ? g_count[i] : 0;
    s[threadIdx.x] = c;
    __syncthreads();
#pragma unroll
    for (int off = 1; off < 256; off <<= 1) {
        int v = (threadIdx.x >= off) ? s[threadIdx.x - off] : 0;
        __syncthreads();
        s[threadIdx.x] += v;
        __syncthreads();
    }
    if (i < N_NODES) g_rowstart[i] = s[threadIdx.x] - c;   // exclusive within block
    if (threadIdx.x == 255) g_blocksum[blockIdx.x] = s[255];
}

__global__ void scan2_kernel() {
    __shared__ int s[512];
    int t = threadIdx.x;
    int v = (t < NB_SCAN) ? g_blocksum[t] : 0;
    s[t] = v;
    __syncthreads();
#pragma unroll
    for (int off = 1; off < 512; off <<= 1) {
        int u = (t >= off) ? s[t - off] : 0;
        __syncthreads();
        s[t] += u;
        __syncthreads();
    }
    if (t < NB_SCAN) g_blocksum[t] = s[t] - v;   // exclusive
}

__global__ void scan3_kernel() {
    int i = blockIdx.x * 256 + threadIdx.x;
    if (i < N_NODES) {
        int r = g_rowstart[i] + g_blocksum[blockIdx.x];
        g_rowstart[i] = r;
        g_cursor[i]   = r;
    }
    if (i == 0) g_rowstart[N_NODES] = N_EDGES;
}

__global__ void scatter_kernel(const int* __restrict__ src, const int* __restrict__ dst) {
    int e = blockIdx.x * blockDim.x + threadIdx.x;
    if (e >= N_EDGES) return;
    int d = dst[e];
    int pos = atomicAdd(&g_cursor[d], 1);
    g_csr_src[pos] = src[e];
}

// ---------------- prep: split + transpose W1 -> bf16 hi/lo [64][512] ----------------
__global__ void prep_w_kernel(const float* __restrict__ W1) {
    int idx = blockIdx.x * blockDim.x + threadIdx.x;   // 0 .. 32767
    int n = idx >> 9;          // 0..63
    int k = idx & 511;         // 0..511
    float w = (k < F_IN) ? W1[k * H_DIM + n] : 0.f;
    __nv_bfloat16 hi = __float2bfloat16(w);
    __nv_bfloat16 lo = __float2bfloat16(w - __bfloat162float(hi));
    g_wt_hi[n * 512 + k] = hi;
    g_wt_lo[n * 512 + k] = lo;
}

// ---------------- GEMM1 via mma.sync bf16 3-term split, reg-prefetch pipelined ----------------
#define MT      128
#define KCH     32
#define NCHUNK  16
#define A_STRIDE 80
#define B_STRIDE 80

__global__ __launch_bounds__(256) void gemm1_mma_kernel(const float* __restrict__ X) {
    __shared__ __align__(16) char smA_hi[MT * A_STRIDE];
    __shared__ __align__(16) char smA_lo[MT * A_STRIDE];
    __shared__ __align__(16) char smB_hi[64 * B_STRIDE];
    __shared__ __align__(16) char smB_lo[64 * B_STRIDE];

    const int tid  = threadIdx.x;
    const int wid  = tid >> 5;
    const int lane = tid & 31;
    const int row0 = blockIdx.x * MT;

    float acc[8][4];
#pragma unroll
    for (int g = 0; g < 8; g++)
#pragma unroll
        for (int j = 0; j < 4; j++) acc[g][j] = 0.f;

    const int a_c4 = tid & 7;
    const int a_r  = tid >> 3;
    const int b_n  = tid >> 2;
    const int b_kg = tid & 3;

    const int frag_m  = (lane >> 2);
    const int frag_kb = (lane & 3) * 4;

    float4 pa[4];
    uint4  pbh, pbl;

    // prefetch chunk 0
    {
        const int k0 = 0;
#pragma unroll
        for (int p = 0; p < 4; p++) {
            int gr = row0 + p * 32 + a_r;
            int gc = k0 + a_c4 * 4;
            pa[p] = make_float4(0.f, 0.f, 0.f, 0.f);
            if (gr < N_NODES && gc < F_IN)
                pa[p] = *(const float4*)(X + (size_t)gr * F_IN + gc);
        }
        pbh = *(const uint4*)((const char*)g_wt_hi + (size_t)b_n * 1024 + (k0 + b_kg * 8) * 2);
        pbl = *(const uint4*)((const char*)g_wt_lo + (size_t)b_n * 1024 + (k0 + b_kg * 8) * 2);
    }

    for (int ch = 0; ch < NCHUNK; ch++) {
        // --- store prefetched chunk into SMEM (convert A to split bf16) ---
#pragma unroll
        for (int p = 0; p < 4; p++) {
            int r = p * 32 + a_r;
            float4 v = pa[p];
            __nv_bfloat16 h0 = __float2bfloat16(v.x), h1 = __float2bfloat16(v.y);
            __nv_bfloat16 h2 = __float2bfloat16(v.z), h3 = __float2bfloat16(v.w);
            uint32_t hiA = (uint32_t)__bfloat16_as_ushort(h0) | ((uint32_t)__bfloat16_as_ushort(h1) << 16);
            uint32_t hiB = (uint32_t)__bfloat16_as_ushort(h2) | ((uint32_t)__bfloat16_as_ushort(h3) << 16);
            uint32_t loA = pack_bf16x2(v.x - __bfloat162float(h0), v.y - __bfloat162float(h1));
            uint32_t loB = pack_bf16x2(v.z - __bfloat162float(h2), v.w - __bfloat162float(h3));
            *(uint2*)(smA_hi + r * A_STRIDE + a_c4 * 8) = make_uint2(hiA, hiB);
            *(uint2*)(smA_lo + r * A_STRIDE + a_c4 * 8) = make_uint2(loA, loB);
        }
        *(uint4*)(smB_hi + b_n * B_STRIDE + b_kg * 16) = pbh;
        *(uint4*)(smB_lo + b_n * B_STRIDE + b_kg * 16) = pbl;
        __syncthreads();

        // --- issue next chunk's global loads (overlap with MMA below) ---
        if (ch + 1 < NCHUNK) {
            const int k0 = (ch + 1) * KCH;
#pragma unroll
            for (int p = 0; p < 4; p++) {
                int gr = row0 + p * 32 + a_r;
                int gc = k0 + a_c4 * 4;
                pa[p] = make_float4(0.f, 0.f, 0.f, 0.f);
                if (gr < N_NODES && gc < F_IN)
                    pa[p] = *(const float4*)(X + (size_t)gr * F_IN + gc);
            }
            pbh = *(const uint4*)((const char*)g_wt_hi + (size_t)b_n * 1024 + (k0 + b_kg * 8) * 2);
            pbl = *(const uint4*)((const char*)g_wt_lo + (size_t)b_n * 1024 + (k0 + b_kg * 8) * 2);
        }

        // --- compute ---
#pragma unroll
        for (int ks = 0; ks < 2; ks++) {
            const int m0   = wid * 16 + frag_m;
            const int koff = ks * 32 + frag_kb;
            uint32_t ahi[4], alo[4];
            ahi[0] = *(const uint32_t*)(smA_hi + m0 * A_STRIDE + koff);
            ahi[1] = *(const uint32_t*)(smA_hi + (m0 + 8) * A_STRIDE + koff);
            ahi[2] = *(const uint32_t*)(smA_hi + m0 * A_STRIDE + koff + 16);
            ahi[3] = *(const uint32_t*)(smA_hi + (m0 + 8) * A_STRIDE + koff + 16);
            alo[0] = *(const uint32_t*)(smA_lo + m0 * A_STRIDE + koff);
            alo[1] = *(const uint32_t*)(smA_lo + (m0 + 8) * A_STRIDE + koff);
            alo[2] = *(const uint32_t*)(smA_lo + m0 * A_STRIDE + koff + 16);
            alo[3] = *(const uint32_t*)(smA_lo + (m0 + 8) * A_STRIDE + koff + 16);
#pragma unroll
            for (int g = 0; g < 8; g++) {
                const int n = g * 8 + frag_m;
                uint32_t bhi[2], blo[2];
                bhi[0] = *(const uint32_t*)(smB_hi + n * B_STRIDE + koff);
                bhi[1] = *(const uint32_t*)(smB_hi + n * B_STRIDE + koff + 16);
                blo[0] = *(const uint32_t*)(smB_lo + n * B_STRIDE + koff);
                blo[1] = *(const uint32_t*)(smB_lo + n * B_STRIDE + koff + 16);
                mma16816(acc[g], ahi, bhi);
                mma16816(acc[g], alo, bhi);
                mma16816(acc[g], ahi, blo);
            }
        }
        __syncthreads();
    }

    // --- epilogue: fragments -> g_h1 ---
    {
        const int m0 = row0 + wid * 16 + frag_m;
        const int nc = (lane & 3) * 2;
#pragma unroll
        for (int g = 0; g < 8; g++) {
            if (m0 < N_NODES)
                *(float2*)(g_h1 + (size_t)m0 * H_DIM + g * 8 + nc) = make_float2(acc[g][0], acc[g][1]);
            if (m0 + 8 < N_NODES)
                *(float2*)(g_h1 + (size_t)(m0 + 8) * H_DIM + g * 8 + nc) = make_float2(acc[g][2], acc[g][3]);
        }
    }
}

// ---------------- layer-1 gather: warp per dst node, fused self-loop+bias+relu ----------------
__global__ __launch_bounds__(256) void agg1_gather_kernel(const float* __restrict__ b1) {
    int node = blockIdx.x * 8 + (threadIdx.x >> 5);
    if (node >= N_NODES) return;
    const int lane = threadIdx.x & 31;
    const int col  = lane * 2;

    const float dis_i = g_dis[node];
    const int start = g_rowstart[node];
    const int end   = g_rowstart[node + 1];

    float2 self = *(const float2*)(g_h1 + (size_t)node * H_DIM + col);
    float d2 = dis_i * dis_i;
    float ax = self.x * d2, ay = self.y * d2;

    for (int j = start; j < end; j++) {
        int s = g_csr_src[j];                       // warp-uniform broadcast
        float nrm = g_dis[s] * dis_i;
        float2 v = *(const float2*)(g_h1 + (size_t)s * H_DIM + col);
        ax += v.x * nrm;
        ay += v.y * nrm;
    }
    float2 bias = *(const float2*)(b1 + col);
    ax = fmaxf(ax + bias.x, 0.f);
    ay = fmaxf(ay + bias.y, 0.f);
    *(float2*)(g_hr + (size_t)node * H_DIM + col) = make_float2(ax, ay);
}

// ---------------- GEMM2: h2[N,10] = h_relu[N,64] @ W2[64,10] ----------------
__global__ __launch_bounds__(256) void gemm2_kernel(const float* __restrict__ W2) {
    __shared__ float Ws[H_DIM * C_DIM];
    for (int i = threadIdx.x; i < H_DIM * C_DIM; i += blockDim.x) Ws[i] = W2[i];
    __syncthreads();
    int row = blockIdx.x * blockDim.x + threadIdx.x;
    if (row >= N_NODES) return;
    float acc[C_DIM];
#pragma unroll
    for (int j = 0; j < C_DIM; j++) acc[j] = 0.f;
    const float4* rp = (const float4*)(g_hr + (size_t)row * H_DIM);
#pragma unroll
    for (int k4 = 0; k4 < H_DIM / 4; k4++) {
        float4 v = rp[k4];
        int k = k4 * 4;
#pragma unroll
        for (int j = 0; j < C_DIM; j++) {
            acc[j] += v.x * Ws[(k + 0) * C_DIM + j]
                    + v.y * Ws[(k + 1) * C_DIM + j]
                    + v.z * Ws[(k + 2) * C_DIM + j]
                    + v.w * Ws[(k + 3) * C_DIM + j];
        }
    }
#pragma unroll
    for (int j = 0; j < C_DIM; j++) g_h2[(size_t)row * C_DIM + j] = acc[j];
}

// ---------------- layer-2 gather: warp per dst node, 3 edges x 10 feats, writes out ----------------
__global__ __launch_bounds__(256) void agg2_gather_kernel(const float* __restrict__ b2,
                                                          float* __restrict__ out) {
    int node = blockIdx.x * 8 + (threadIdx.x >> 5);
    if (node >= N_NODES) return;
    const int lane = threadIdx.x & 31;
    const int f  = lane % 10;
    const int eo = lane / 10;

    const float dis_i = g_dis[node];
    const int start = g_rowstart[node];
    const int end   = g_rowstart[node + 1];

    float acc = 0.f;
    if (lane < 30) {
        for (int j = start + eo; j < end; j += 3) {
            int s = g_csr_src[j];
            float nrm = g_dis[s] * dis_i;
            acc += g_h2[(size_t)s * C_DIM + f] * nrm;
        }
    }
    float a1 = __shfl_sync(0xFFFFFFFFu, acc, lane + 10 < 32 ? lane + 10 : lane);
    float a2 = __shfl_sync(0xFFFFFFFFu, acc, lane + 20 < 32 ? lane + 20 : lane);
    if (lane < 10) {
        acc += a1 + a2;
        float self = g_h2[(size_t)node * C_DIM + f] * dis_i * dis_i;
        out[(size_t)node * C_DIM + f] = acc + self + __ldg(&b2[f]);
    }
}

// ---------------- launch ----------------
extern "C" void kernel_launch(void* const* d_in, const int* in_sizes, int n_in,
                              void* d_out, int out_size) {
    const float* x  = (const float*)d_in[0];
    const int*   ei = (const int*)d_in[1];
    const float* W1 = (const float*)d_in[2];
    const float* b1 = (const float*)d_in[3];
    const float* W2 = (const float*)d_in[4];
    const float* b2 = (const float*)d_in[5];
    float* out = (float*)d_out;

    const int E = in_sizes[1] / 2;         // 1600000
    const int* src = ei;
    const int* dst = ei + E;

    const int T = 256;

    // graph preprocessing
    init_kernel<<<NB_SCAN, T>>>();
    degree_kernel<<<(E + T - 1) / T, T>>>(dst);
    dis_kernel<<<NB_SCAN, T>>>();
    scan1_kernel<<<NB_SCAN, T>>>();
    scan2_kernel<<<1, 512>>>();
    scan3_kernel<<<NB_SCAN, T>>>();
    scatter_kernel<<<(E + T - 1) / T, T>>>(src, dst);

    // layer 1
    prep_w_kernel<<<128, 256>>>(W1);
    gemm1_mma_kernel<<<(N_NODES + MT - 1) / MT, 256>>>(x);
    agg1_gather_kernel<<<(N_NODES + 7) / 8, 256>>>(b1);

    // layer 2
    gemm2_kernel<<<(N_NODES + T - 1) / T, T>>>(W2);
    agg2_gather_kernel<<<(N_NODES + 7) / 8, 256>>>(b2, out);
}